// round 12
// baseline (speedup 1.0000x reference)
#include <cuda_runtime.h>
#include <math.h>

// ---------------- problem constants ----------------
#define BS      2
#define DMODEL  256
#define HH      28
#define NTOK    784          // 28*28
#define WWIN    7
#define MW      4            // windows per side
#define NW      16
#define WS      49
#define KTOP    8
#define NHEAD   8
#define DH      32
#define DFF     512

// dedup attention: 784 token keys + 16 mean keys = 800, padded to 832
#define NCH2    4
#define CH2     208          // keys per chunk
#define KT      16           // key tile

typedef unsigned long long ull;

// ---------------- PDL: overlap launch/dispatch with predecessor tail ----------------
#define PDL_DEP  asm volatile("griddepcontrol.launch_dependents;" ::: "memory")
#define PDL_WAIT asm volatile("griddepcontrol.wait;" ::: "memory")

// ---------------- f32x2 packed math helpers ----------------
__device__ __forceinline__ ull pack2(float a, float b) {
    ull r;
    asm("mov.b64 %0, {%1, %2};" : "=l"(r) : "f"(a), "f"(b));
    return r;
}
__device__ __forceinline__ void unpack2(ull p, float& a, float& b) {
    asm("mov.b64 {%0, %1}, %2;" : "=f"(a), "=f"(b) : "l"(p));
}
__device__ __forceinline__ void ffma2(ull& d, ull a, ull b) {
    asm("fma.rn.f32x2 %0, %1, %2, %0;" : "+l"(d) : "l"(a), "l"(b));
}
__device__ __forceinline__ void add2(ull& d, ull a) {
    asm("add.rn.f32x2 %0, %0, %1;" : "+l"(d) : "l"(a));
}

// ---------------- scratch (device globals; no allocs allowed) ----------------
__device__ float g_xf  [BS*NTOK*DMODEL];
__device__ float g_q   [BS*NTOK*DMODEL];
__device__ float g_k   [BS*NTOK*DMODEL];
__device__ float g_v   [BS*NTOK*DMODEL];
__device__ float g_qm  [BS*NW*DMODEL];
__device__ float g_km  [BS*NW*DMODEL];
__device__ float g_vm  [BS*NW*DMODEL];
__device__ int   g_icnt[BS*NW];
__device__ float g_pl  [BS*NHEAD*NCH2*NTOK];
__device__ float g_pacc[BS*NHEAD*NCH2*NTOK*DH];
__device__ float g_msg [BS*NTOK*DMODEL];
__device__ float g_msg2[BS*NTOK*DMODEL];
__device__ float g_mesg[BS*NTOK*DFF];
__device__ float g_y1  [BS*NTOK*DFF];
__device__ float g_y2  [BS*NTOK*DFF];
__device__ float g_z   [BS*NTOK*DMODEL];

// ---------------- x (b,d,hw) -> xf (b,hw,d) ----------------
__global__ void k_transpose(const float* __restrict__ x, float* __restrict__ xf) {
    PDL_DEP; PDL_WAIT;
    __shared__ float tile[32][33];
    int b  = blockIdx.z;
    int c0 = blockIdx.y * 32, n0 = blockIdx.x * 32;
    int tx = threadIdx.x, ty = threadIdx.y;   // (32, 8)
    #pragma unroll
    for (int i = 0; i < 32; i += 8) {
        int c = c0 + ty + i, n = n0 + tx;
        if (c < DMODEL && n < NTOK) tile[ty + i][tx] = x[(b * DMODEL + c) * NTOK + n];
    }
    __syncthreads();
    #pragma unroll
    for (int i = 0; i < 32; i += 8) {
        int n = n0 + ty + i, c = c0 + tx;
        if (n < NTOK && c < DMODEL) xf[(b * NTOK + n) * DMODEL + c] = tile[tx][ty + i];
    }
}

// ---------------- double-buffered packed-FMA GEMM ----------------
// C[M,N] = act(A[M,K] @ B[N,K]^T + bias). 64x64 tile, 256 threads,
// BK=16, 2 smem buffers, 1 syncthreads per k-iter. N%64==0, K%16==0.
__device__ __forceinline__ void gemm6_body(const float* __restrict__ A, const float* __restrict__ B,
                                           const float* __restrict__ bias, float* __restrict__ C,
                                           int M, int N, int K, int act, int by, int bx) {
    __shared__ __align__(16) float As[2][16][68];
    __shared__ __align__(16) float Bs[2][16][68];
    int bm = by * 64, bn = bx * 64;
    int tid = threadIdx.x;          // 0..255
    int tr = tid >> 4;              // 0..15
    int tc = tid & 15;              // 0..15
    int lr = tid >> 2, lk4 = tid & 3;

    ull acc[4][2];
    #pragma unroll
    for (int i = 0; i < 4; i++) { acc[i][0] = 0ull; acc[i][1] = 0ull; }

    int ga = bm + lr, gb = bn + lr;
    const float4 z4 = make_float4(0.f, 0.f, 0.f, 0.f);

    // preload tile 0
    float4 av = (ga < M) ? *(const float4*)&A[(size_t)ga * K + lk4 * 4] : z4;
    float4 bv = (gb < N) ? *(const float4*)&B[(size_t)gb * K + lk4 * 4] : z4;
    As[0][lk4 * 4 + 0][lr] = av.x; As[0][lk4 * 4 + 1][lr] = av.y;
    As[0][lk4 * 4 + 2][lr] = av.z; As[0][lk4 * 4 + 3][lr] = av.w;
    Bs[0][lk4 * 4 + 0][lr] = bv.x; Bs[0][lk4 * 4 + 1][lr] = bv.y;
    Bs[0][lk4 * 4 + 2][lr] = bv.z; Bs[0][lk4 * 4 + 3][lr] = bv.w;
    __syncthreads();

    int niter = K >> 4;
    for (int it = 0; it < niter; it++) {
        int cur = it & 1;
        float4 nav, nbv;
        if (it + 1 < niter) {
            int k0 = (it + 1) << 4;
            nav = (ga < M) ? *(const float4*)&A[(size_t)ga * K + k0 + lk4 * 4] : z4;
            nbv = (gb < N) ? *(const float4*)&B[(size_t)gb * K + k0 + lk4 * 4] : z4;
        }
        #pragma unroll
        for (int kq = 0; kq < 16; kq++) {
            float4 a4 = *(const float4*)&As[cur][kq][tr * 4];
            ulonglong2 bb = *(const ulonglong2*)&Bs[cur][kq][tc * 4];
            ull pa0 = pack2(a4.x, a4.x);
            ull pa1 = pack2(a4.y, a4.y);
            ull pa2 = pack2(a4.z, a4.z);
            ull pa3 = pack2(a4.w, a4.w);
            ffma2(acc[0][0], pa0, bb.x); ffma2(acc[0][1], pa0, bb.y);
            ffma2(acc[1][0], pa1, bb.x); ffma2(acc[1][1], pa1, bb.y);
            ffma2(acc[2][0], pa2, bb.x); ffma2(acc[2][1], pa2, bb.y);
            ffma2(acc[3][0], pa3, bb.x); ffma2(acc[3][1], pa3, bb.y);
        }
        if (it + 1 < niter) {
            int nb = cur ^ 1;
            As[nb][lk4 * 4 + 0][lr] = nav.x; As[nb][lk4 * 4 + 1][lr] = nav.y;
            As[nb][lk4 * 4 + 2][lr] = nav.z; As[nb][lk4 * 4 + 3][lr] = nav.w;
            Bs[nb][lk4 * 4 + 0][lr] = nbv.x; Bs[nb][lk4 * 4 + 1][lr] = nbv.y;
            Bs[nb][lk4 * 4 + 2][lr] = nbv.z; Bs[nb][lk4 * 4 + 3][lr] = nbv.w;
        }
        __syncthreads();
    }

    int c0 = bn + tc * 4;
    #pragma unroll
    for (int i = 0; i < 4; i++) {
        int r = bm + tr * 4 + i;
        if (r >= M) continue;
        float4 o;
        unpack2(acc[i][0], o.x, o.y);
        unpack2(acc[i][1], o.z, o.w);
        if (bias) {
            o.x += bias[c0 + 0]; o.y += bias[c0 + 1];
            o.z += bias[c0 + 2]; o.w += bias[c0 + 3];
        }
        if (act == 1) {
            o.x = fmaxf(o.x, 0.f); o.y = fmaxf(o.y, 0.f);
            o.z = fmaxf(o.z, 0.f); o.w = fmaxf(o.w, 0.f);
        }
        *(float4*)&C[(size_t)r * N + c0] = o;
    }
}

__global__ __launch_bounds__(256) void k_gemm6(const float* __restrict__ A, const float* __restrict__ B,
                                               const float* __restrict__ bias, float* __restrict__ C,
                                               int M, int N, int K, int act) {
    PDL_DEP; PDL_WAIT;
    gemm6_body(A, B, bias, C, M, N, K, act, blockIdx.y, blockIdx.x);
}

// fused QKV: grid.x = 12 (3 weights x 4 col tiles), grid.y = 25
__global__ __launch_bounds__(256) void k_qkv(const float* __restrict__ A,
                                             const float* __restrict__ Wq, const float* __restrict__ Wk,
                                             const float* __restrict__ Wv,
                                             float* __restrict__ q, float* __restrict__ k, float* __restrict__ v) {
    PDL_DEP; PDL_WAIT;
    int sel = blockIdx.x >> 2;
    const float* B = (sel == 0) ? Wq : (sel == 1) ? Wk : Wv;
    float* C = (sel == 0) ? q : (sel == 1) ? k : v;
    gemm6_body(A, B, nullptr, C, BS * NTOK, DMODEL, DMODEL, 0, blockIdx.y, blockIdx.x & 3);
}

// ---------------- per-window means of q,k,v (+ zero topk counters) ----------------
__global__ void k_means(const float* __restrict__ q, const float* __restrict__ k,
                        const float* __restrict__ v,
                        float* __restrict__ qm, float* __restrict__ km, float* __restrict__ vm,
                        int* __restrict__ icnt) {
    PDL_DEP; PDL_WAIT;
    int b = blockIdx.x / NW, w = blockIdx.x % NW;
    int c = threadIdx.x;
    if (w == 0 && c < NW) icnt[b * NW + c] = 0;
    int wr = w / MW, wc = w % MW;
    float sq = 0.f, sk = 0.f, sv = 0.f;
    for (int p = 0; p < WS; p++) {
        int pr = p / WWIN, pc = p % WWIN;
        int n  = (wr * WWIN + pr) * HH + wc * WWIN + pc;
        int o  = (b * NTOK + n) * DMODEL + c;
        sq += q[o]; sk += k[o]; sv += v[o];
    }
    int o = (b * NW + w) * DMODEL + c;
    qm[o] = sq * (1.f / 49.f);
    km[o] = sk * (1.f / 49.f);
    vm[o] = sv * (1.f / 49.f);
}

// ---------------- topk via rank counting (exact jax top_k tie semantics) ----------------
// grid (NW, BS), 256 threads. Window j selected by query i iff rank(sim[i][j]) < 8,
// rank = #{u : s_u > s_j or (s_u == s_j and u < j)}.
__global__ __launch_bounds__(256) void k_topk(const float* __restrict__ qm, const float* __restrict__ km,
                                              int* __restrict__ icnt) {
    PDL_DEP; PDL_WAIT;
    int i = blockIdx.x, b = blockIdx.y;
    __shared__ __align__(16) float4 q4s[64];
    __shared__ float red[NW][17];
    __shared__ float simr[NW];
    int t = threadIdx.x;
    if (t < 64) q4s[t] = ((const float4*)qm)[(b * NW + i) * 64 + t];
    __syncthreads();
    int j = t >> 4, part = t & 15;
    const float4* krow = (const float4*)km + (b * NW + j) * 64;
    float s = 0.f;
    #pragma unroll
    for (int u = 0; u < 4; u++) {
        float4 kk = krow[part * 4 + u];
        float4 qq = q4s[part * 4 + u];
        s += qq.x * kk.x + qq.y * kk.y + qq.z * kk.z + qq.w * kk.w;
    }
    red[j][part] = s;
    __syncthreads();
    if (part == 0) {
        float tot = 0.f;
        #pragma unroll
        for (int u = 0; u < 16; u++) tot += red[j][u];
        simr[j] = tot;
    }
    __syncthreads();
    if (t < NW) {
        float mine = simr[t];
        int rank = 0;
        #pragma unroll
        for (int u = 0; u < NW; u++) {
            float o = simr[u];
            rank += (o > mine) || (o == mine && u < t);
        }
        if (rank < KTOP) atomicAdd(&icnt[b * NW + t], 1);
    }
}

// ---------------- dedup attention over 800 unique keys (padded to 832) ----------------
// key row r: r<784 -> token r (weight = multiplicity of its window)
//            784<=r<800 -> mean r-784 (weight 16); r>=800 -> pad (weight 0)
// grid (7, NHEAD, BS*NCH2), block 128. Scores tiny -> softmax without max pass.
__global__ __launch_bounds__(128) void k_attn(const float* __restrict__ qb,
                                              const float* __restrict__ kb,
                                              const float* __restrict__ vb,
                                              const float* __restrict__ km,
                                              const float* __restrict__ vm,
                                              const int* __restrict__ icnt,
                                              float* __restrict__ pl,
                                              float* __restrict__ pacc) {
    PDL_DEP; PDL_WAIT;
    int qt0   = blockIdx.x * 128;
    int h     = blockIdx.y;
    int b     = blockIdx.z / NCH2;
    int chunk = blockIdx.z % NCH2;
    int t = threadIdx.x;
    int l = qt0 + t;
    int lq = (l < NTOK) ? l : 0;
    int w = lq / WS, p = lq % WS;
    int n = ((w / MW) * WWIN + p / WWIN) * HH + (w % MW) * WWIN + (p % WWIN);

    const ulonglong2* qrow = (const ulonglong2*)(qb + ((size_t)(b * NTOK + n) * DMODEL + h * DH));
    ull qp[16];
    #pragma unroll
    for (int i = 0; i < 8; i++) {
        ulonglong2 qq = qrow[i];
        qp[2 * i + 0] = qq.x;
        qp[2 * i + 1] = qq.y;
    }

    __shared__ __align__(16) float4 Ks[KT][DH / 4];
    __shared__ __align__(16) float4 Vs[KT][DH / 4];
    __shared__ float  wgt[KT];
    __shared__ float  scnt[NW];
    if (t < NW) scnt[t] = (float)icnt[b * NW + t];

    float lsum = 0.f;
    ull acc[16];
    #pragma unroll
    for (int d = 0; d < 16; d++) acc[d] = 0ull;
    const float scale = 0.17677669529663687f;   // 32^-0.5

    int s0 = chunk * CH2;
    for (int tile = 0; tile < CH2 / KT; tile++) {
        int sbase = s0 + tile * KT;
        __syncthreads();
        // load 2*KT rows x 8 float4 = 256 float4, 128 threads -> 2 each
        #pragma unroll
        for (int i = 0; i < 2; i++) {
            int f = i * 128 + t;
            int r = f >> 3, c4 = f & 7;
            int rr = (r < KT) ? r : r - KT;
            int gr = sbase + rr;
            const float4* src;
            int rowbase;
            if (gr < NTOK) {
                src = (r < KT) ? (const float4*)kb : (const float4*)vb;
                rowbase = b * NTOK + gr;
            } else {
                int mi = gr - NTOK;
                if (mi >= NW) mi = 0;            // pad rows: weight 0, data harmless
                src = (r < KT) ? (const float4*)km : (const float4*)vm;
                rowbase = b * NW + mi;
            }
            float4 val = src[rowbase * (DMODEL / 4) + h * (DH / 4) + c4];
            if (r < KT) Ks[r][c4] = val; else Vs[r - KT][c4] = val;
        }
        if (t < KT) {
            int gr = sbase + t;
            float wv;
            if (gr < NTOK) {
                int win = (gr / (WWIN * HH)) * MW + (gr % HH) / WWIN;
                wv = scnt[win];
            } else wv = (gr < NTOK + NW) ? 16.f : 0.f;
            wgt[t] = wv;
        }
        __syncthreads();
        #pragma unroll 8
        for (int kk = 0; kk < KT; kk++) {
            const ulonglong2* krow = (const ulonglong2*)&Ks[kk][0];
            // 4 independent packed score chains (depth 4 instead of 16)
            ull sa = 0ull, sb = 0ull, sc = 0ull, sd = 0ull;
            #pragma unroll
            for (int c = 0; c < 2; c++) {
                ulonglong2 kv0 = krow[4 * c + 0];
                ulonglong2 kv1 = krow[4 * c + 1];
                ulonglong2 kv2 = krow[4 * c + 2];
                ulonglong2 kv3 = krow[4 * c + 3];
                ffma2(sa, qp[8 * c + 0], kv0.x); ffma2(sb, qp[8 * c + 1], kv0.y);
                ffma2(sc, qp[8 * c + 2], kv1.x); ffma2(sd, qp[8 * c + 3], kv1.y);
                ffma2(sa, qp[8 * c + 4], kv2.x); ffma2(sb, qp[8 * c + 5], kv2.y);
                ffma2(sc, qp[8 * c + 6], kv3.x); ffma2(sd, qp[8 * c + 7], kv3.y);
            }
            add2(sa, sb); add2(sc, sd); add2(sa, sc);
            float slo, shi;
            unpack2(sa, slo, shi);
            float pe = wgt[kk] * __expf((slo + shi) * scale);
            lsum += pe;
            ull pp = pack2(pe, pe);
            const ulonglong2* vrow = (const ulonglong2*)&Vs[kk][0];
            #pragma unroll
            for (int c = 0; c < 8; c++) {
                ulonglong2 vv = vrow[c];
                ffma2(acc[2 * c + 0], pp, vv.x);
                ffma2(acc[2 * c + 1], pp, vv.y);
            }
        }
    }
    if (l < NTOK) {
        int pbase = ((b * NHEAD + h) * NCH2 + chunk) * NTOK + l;
        pl[pbase] = lsum;
        #pragma unroll
        for (int d = 0; d < 16; d++) {
            float f0, f1;
            unpack2(acc[d], f0, f1);
            pacc[(size_t)pbase * DH + 2 * d + 0] = f0;
            pacc[(size_t)pbase * DH + 2 * d + 1] = f1;
        }
    }
}

// ---------------- combine split-K partials -> msg ----------------
__global__ void k_combine(const float* __restrict__ pl, const float* __restrict__ pacc,
                          float* __restrict__ msg) {
    PDL_DEP; PDL_WAIT;
    int gq   = blockIdx.x * 8 + (threadIdx.x >> 5);   // BS*NHEAD*NTOK units
    int lane = threadIdx.x & 31;
    int b = gq / (NHEAD * NTOK);
    int rem = gq % (NHEAD * NTOK);
    int h = rem / NTOK, l = rem % NTOK;
    float Ls = 0.f, o = 0.f;
    #pragma unroll
    for (int c = 0; c < NCH2; c++) {
        int pbase = ((b * NHEAD + h) * NCH2 + c) * NTOK + l;
        Ls += pl[pbase];
        o  += pacc[(size_t)pbase * DH + lane];
    }
    msg[(b * NTOK + l) * DMODEL + h * DH + lane] = o / Ls;
}

// ---------------- LN1 + concat: message = [xf | LN(msg2)], shfl reductions ----------------
__global__ void k_ln1(const float* __restrict__ msg2, const float* __restrict__ xf,
                      const float* __restrict__ g, const float* __restrict__ bta,
                      float* __restrict__ message) {
    PDL_DEP; PDL_WAIT;
    int row = blockIdx.x;       // 0..BS*NTOK-1
    int c = threadIdx.x;        // 256
    int lane = c & 31, wid = c >> 5;
    __shared__ float red[16];
    float v = msg2[row * DMODEL + c];
    float s = v;
    #pragma unroll
    for (int o = 16; o > 0; o >>= 1) s += __shfl_xor_sync(0xffffffff, s, o);
    if (lane == 0) red[wid] = s;
    __syncthreads();
    float mu = 0.f;
    #pragma unroll
    for (int u = 0; u < 8; u++) mu += red[u];
    mu *= (1.f / DMODEL);
    float dv = v - mu;
    float sq = dv * dv;
    #pragma unroll
    for (int o = 16; o > 0; o >>= 1) sq += __shfl_xor_sync(0xffffffff, sq, o);
    if (lane == 0) red[8 + wid] = sq;
    __syncthreads();
    float var = 0.f;
    #pragma unroll
    for (int u = 0; u < 8; u++) var += red[8 + u];
    var *= (1.f / DMODEL);
    float outv = dv * rsqrtf(var + 1e-5f) * g[c] + bta[c];
    message[row * DFF + DMODEL + c] = outv;
    message[row * DFF + c] = xf[row * DMODEL + c];
}

// ---------------- depthwise 3x3 conv + bias + exact gelu ----------------
__global__ void k_dwconv(const float* __restrict__ y1, const float* __restrict__ dww,
                         const float* __restrict__ dwb, float* __restrict__ y2) {
    PDL_DEP; PDL_WAIT;
    int b = blockIdx.y;
    int nn = blockIdx.x;        // 0..783
    int c = threadIdx.x;        // 512
    int r = nn / HH, col = nn % HH;
    float s = 0.f;
    #pragma unroll
    for (int dr = -1; dr <= 1; dr++)
        #pragma unroll
        for (int dc = -1; dc <= 1; dc++) {
            int rr = r + dr, cc = col + dc;
            if (rr >= 0 && rr < HH && cc >= 0 && cc < HH)
                s += y1[(b * NTOK + rr * HH + cc) * DFF + c] * dww[c * 9 + (dr + 1) * 3 + (dc + 1)];
        }
    s += dwb[c];
    float gl = 0.5f * s * (1.f + erff(s * 0.70710678118654752f));
    y2[(b * NTOK + nn) * DFF + c] = gl;
}

// ---------------- LN2 + residual + coalesced transposed store ----------------
// grid (25, 2), block 256 (8 warps x 4 rows = 32 tokens per block)
__global__ __launch_bounds__(256) void k_ln2(const float* __restrict__ z, const float* __restrict__ xf,
                                             const float* __restrict__ g, const float* __restrict__ bta,
                                             float* __restrict__ out) {
    PDL_DEP; PDL_WAIT;
    __shared__ float tile[DMODEL][33];
    int b = blockIdx.y, n0 = blockIdx.x * 32;
    int rows = NTOK - n0; if (rows > 32) rows = 32;
    int wid = threadIdx.x >> 5, lane = threadIdx.x & 31;

    #pragma unroll
    for (int i = 0; i < 4; i++) {
        int rl = wid * 4 + i;
        if (rl >= rows) break;
        int row = b * NTOK + n0 + rl;
        float vals[8];
        float s = 0.f;
        #pragma unroll
        for (int j = 0; j < 8; j++) {
            vals[j] = z[(size_t)row * DMODEL + lane + j * 32];
            s += vals[j];
        }
        #pragma unroll
        for (int o = 16; o > 0; o >>= 1) s += __shfl_xor_sync(0xffffffff, s, o);
        float mu = s * (1.f / DMODEL);
        float sq = 0.f;
        #pragma unroll
        for (int j = 0; j < 8; j++) { float d = vals[j] - mu; sq += d * d; }
        #pragma unroll
        for (int o = 16; o > 0; o >>= 1) sq += __shfl_xor_sync(0xffffffff, sq, o);
        float rs = rsqrtf(sq * (1.f / DMODEL) + 1e-5f);
        #pragma unroll
        for (int j = 0; j < 8; j++) {
            int c = lane + j * 32;
            float o2 = (vals[j] - mu) * rs * g[c] + bta[c] + xf[(size_t)row * DMODEL + c];
            tile[c][rl] = o2;
        }
    }
    __syncthreads();
    if (lane < rows) {
        #pragma unroll
        for (int i = 0; i < 32; i++) {
            int c = wid * 32 + i;
            out[((size_t)b * DMODEL + c) * NTOK + n0 + lane] = tile[c][lane];
        }
    }
}

// ---------------- host launcher ----------------
static float* symf(const void* s) { void* p = nullptr; cudaGetSymbolAddress(&p, s); return (float*)p; }

template <typename... T>
static void pdl_launch(void (*fn)(T...), dim3 g, dim3 b, T... a) {
    void* args[] = { (void*)&a... };
    cudaLaunchConfig_t cfg = {};
    cfg.gridDim = g; cfg.blockDim = b;
    cfg.dynamicSmemBytes = 0; cfg.stream = 0;
    cudaLaunchAttribute attr;
    attr.id = cudaLaunchAttributeProgrammaticStreamSerialization;
    attr.val.programmaticStreamSerializationAllowed = 1;
    cfg.attrs = &attr; cfg.numAttrs = 1;
    cudaLaunchKernelExC(&cfg, (const void*)fn, args);
}

extern "C" void kernel_launch(void* const* d_in, const int* in_sizes, int n_in,
                              void* d_out, int out_size) {
    const float* x    = (const float*)d_in[0];
    const float* Wq   = (const float*)d_in[1];
    const float* Wk   = (const float*)d_in[2];
    const float* Wv   = (const float*)d_in[3];
    const float* Wm   = (const float*)d_in[4];
    const float* ln1g = (const float*)d_in[5];
    const float* ln1b = (const float*)d_in[6];
    const float* fc1w = (const float*)d_in[7];
    const float* fc1b = (const float*)d_in[8];
    const float* dww  = (const float*)d_in[9];
    const float* dwb  = (const float*)d_in[10];
    const float* fc2w = (const float*)d_in[11];
    const float* fc2b = (const float*)d_in[12];
    const float* ln2g = (const float*)d_in[13];
    const float* ln2b = (const float*)d_in[14];
    float* out = (float*)d_out;

    float* xf   = symf(g_xf);
    float* q    = symf(g_q);
    float* k    = symf(g_k);
    float* v    = symf(g_v);
    float* qm   = symf(g_qm);
    float* km   = symf(g_km);
    float* vm   = symf(g_vm);
    int*   icnt = (int*)symf(g_icnt);
    float* pl   = symf(g_pl);
    float* pacc = symf(g_pacc);
    float* msg  = symf(g_msg);
    float* msg2 = symf(g_msg2);
    float* mesg = symf(g_mesg);
    float* y1   = symf(g_y1);
    float* y2   = symf(g_y2);
    float* z    = symf(g_z);

    const int M = BS * NTOK;   // 1568

    pdl_launch(k_transpose, dim3(25, 8, BS), dim3(32, 8), x, xf);

    pdl_launch(k_qkv, dim3(12, 25), dim3(256),
               (const float*)xf, Wq, Wk, Wv, q, k, v);

    pdl_launch(k_means, dim3(BS * NW), dim3(DMODEL),
               (const float*)q, (const float*)k, (const float*)v, qm, km, vm, icnt);
    pdl_launch(k_topk, dim3(NW, BS), dim3(256),
               (const float*)qm, (const float*)km, icnt);

    pdl_launch(k_attn, dim3(7, NHEAD, BS * NCH2), dim3(128),
               (const float*)q, (const float*)k, (const float*)v,
               (const float*)km, (const float*)vm, (const int*)icnt, pl, pacc);
    pdl_launch(k_combine, dim3((BS * NHEAD * NTOK) / 8), dim3(256),
               (const float*)pl, (const float*)pacc, msg);

    pdl_launch(k_gemm6, dim3(4, 25), dim3(256),
               (const float*)msg, Wm, (const float*)nullptr, msg2, M, DMODEL, DMODEL, 0);
    pdl_launch(k_ln1, dim3(M), dim3(DMODEL),
               (const float*)msg2, (const float*)xf, ln1g, ln1b, mesg);

    pdl_launch(k_gemm6, dim3(8, 25), dim3(256),
               (const float*)mesg, fc1w, fc1b, y1, M, DFF, DFF, 1);
    pdl_launch(k_dwconv, dim3(NTOK, BS), dim3(DFF),
               (const float*)y1, dww, dwb, y2);
    pdl_launch(k_gemm6, dim3(4, 25), dim3(256),
               (const float*)y2, fc2w, fc2b, z, M, DMODEL, DFF, 0);

    pdl_launch(k_ln2, dim3(25, BS), dim3(256),
               (const float*)z, (const float*)xf, ln2g, ln2b, out);
}

// round 15
// speedup vs baseline: 1.2673x; 1.2673x over previous
#include <cuda_runtime.h>
#include <math.h>

// ---------------- problem constants ----------------
#define BS      2
#define DMODEL  256
#define HH      28
#define NTOK    784          // 28*28
#define WWIN    7
#define MW      4            // windows per side
#define NW      16
#define WS      49
#define KTOP    8
#define NHEAD   8
#define DH      32
#define DFF     512

// dedup attention: 784 token keys + 16 mean keys = 800, padded to 832
#define NCH2    4
#define CH2     208          // keys per chunk
#define KT      16           // key tile

typedef unsigned long long ull;

// ---------------- f32x2 packed math helpers ----------------
__device__ __forceinline__ ull pack2(float a, float b) {
    ull r;
    asm("mov.b64 %0, {%1, %2};" : "=l"(r) : "f"(a), "f"(b));
    return r;
}
__device__ __forceinline__ void unpack2(ull p, float& a, float& b) {
    asm("mov.b64 {%0, %1}, %2;" : "=f"(a), "=f"(b) : "l"(p));
}
__device__ __forceinline__ void ffma2(ull& d, ull a, ull b) {
    asm("fma.rn.f32x2 %0, %1, %2, %0;" : "+l"(d) : "l"(a), "l"(b));
}
__device__ __forceinline__ void add2(ull& d, ull a) {
    asm("add.rn.f32x2 %0, %0, %1;" : "+l"(d) : "l"(a));
}

// ---------------- scratch (device globals; no allocs allowed) ----------------
__device__ float g_xf  [BS*NTOK*DMODEL];
__device__ float g_q   [BS*NTOK*DMODEL];
__device__ float g_k   [BS*NTOK*DMODEL];
__device__ float g_v   [BS*NTOK*DMODEL];
__device__ float g_qm  [BS*NW*DMODEL];
__device__ float g_km  [BS*NW*DMODEL];
__device__ float g_vm  [BS*NW*DMODEL];
__device__ int   g_icnt[BS*NW];
__device__ float g_pl  [BS*NHEAD*NCH2*NTOK];
__device__ float g_pacc[BS*NHEAD*NCH2*NTOK*DH];
__device__ float g_msg [BS*NTOK*DMODEL];
__device__ float g_msg2[BS*NTOK*DMODEL];
__device__ float g_mesg[BS*NTOK*DFF];
__device__ float g_y1  [BS*NTOK*DFF];
__device__ float g_y2  [BS*NTOK*DFF];
__device__ float g_z   [BS*NTOK*DMODEL];

// ---------------- x (b,d,hw) -> xf (b,hw,d) ----------------
__global__ void k_transpose(const float* __restrict__ x, float* __restrict__ xf) {
    __shared__ float tile[32][33];
    int b  = blockIdx.z;
    int c0 = blockIdx.y * 32, n0 = blockIdx.x * 32;
    int tx = threadIdx.x, ty = threadIdx.y;   // (32, 8)
    #pragma unroll
    for (int i = 0; i < 32; i += 8) {
        int c = c0 + ty + i, n = n0 + tx;
        if (c < DMODEL && n < NTOK) tile[ty + i][tx] = x[(b * DMODEL + c) * NTOK + n];
    }
    __syncthreads();
    #pragma unroll
    for (int i = 0; i < 32; i += 8) {
        int n = n0 + ty + i, c = c0 + tx;
        if (n < NTOK && c < DMODEL) xf[(b * NTOK + n) * DMODEL + c] = tile[tx][ty + i];
    }
}

// ---------------- double-buffered packed-FMA GEMM ----------------
// C[M,N] = act(A[M,K] @ B[N,K]^T + bias). 64x64 tile, 256 threads,
// BK=16, 2 smem buffers, 1 syncthreads per k-iter. N%64==0, K%16==0.
__device__ __forceinline__ void gemm6_body(const float* __restrict__ A, const float* __restrict__ B,
                                           const float* __restrict__ bias, float* __restrict__ C,
                                           int M, int N, int K, int act, int by, int bx) {
    __shared__ __align__(16) float As[2][16][68];
    __shared__ __align__(16) float Bs[2][16][68];
    int bm = by * 64, bn = bx * 64;
    int tid = threadIdx.x;          // 0..255
    int tr = tid >> 4;              // 0..15
    int tc = tid & 15;              // 0..15
    int lr = tid >> 2, lk4 = tid & 3;

    ull acc[4][2];
    #pragma unroll
    for (int i = 0; i < 4; i++) { acc[i][0] = 0ull; acc[i][1] = 0ull; }

    int ga = bm + lr, gb = bn + lr;
    const float4 z4 = make_float4(0.f, 0.f, 0.f, 0.f);

    // preload tile 0
    float4 av = (ga < M) ? *(const float4*)&A[(size_t)ga * K + lk4 * 4] : z4;
    float4 bv = (gb < N) ? *(const float4*)&B[(size_t)gb * K + lk4 * 4] : z4;
    As[0][lk4 * 4 + 0][lr] = av.x; As[0][lk4 * 4 + 1][lr] = av.y;
    As[0][lk4 * 4 + 2][lr] = av.z; As[0][lk4 * 4 + 3][lr] = av.w;
    Bs[0][lk4 * 4 + 0][lr] = bv.x; Bs[0][lk4 * 4 + 1][lr] = bv.y;
    Bs[0][lk4 * 4 + 2][lr] = bv.z; Bs[0][lk4 * 4 + 3][lr] = bv.w;
    __syncthreads();

    int niter = K >> 4;
    for (int it = 0; it < niter; it++) {
        int cur = it & 1;
        float4 nav, nbv;
        if (it + 1 < niter) {
            int k0 = (it + 1) << 4;
            nav = (ga < M) ? *(const float4*)&A[(size_t)ga * K + k0 + lk4 * 4] : z4;
            nbv = (gb < N) ? *(const float4*)&B[(size_t)gb * K + k0 + lk4 * 4] : z4;
        }
        #pragma unroll
        for (int kq = 0; kq < 16; kq++) {
            float4 a4 = *(const float4*)&As[cur][kq][tr * 4];
            ulonglong2 bb = *(const ulonglong2*)&Bs[cur][kq][tc * 4];
            ull pa0 = pack2(a4.x, a4.x);
            ull pa1 = pack2(a4.y, a4.y);
            ull pa2 = pack2(a4.z, a4.z);
            ull pa3 = pack2(a4.w, a4.w);
            ffma2(acc[0][0], pa0, bb.x); ffma2(acc[0][1], pa0, bb.y);
            ffma2(acc[1][0], pa1, bb.x); ffma2(acc[1][1], pa1, bb.y);
            ffma2(acc[2][0], pa2, bb.x); ffma2(acc[2][1], pa2, bb.y);
            ffma2(acc[3][0], pa3, bb.x); ffma2(acc[3][1], pa3, bb.y);
        }
        if (it + 1 < niter) {
            int nb = cur ^ 1;
            As[nb][lk4 * 4 + 0][lr] = nav.x; As[nb][lk4 * 4 + 1][lr] = nav.y;
            As[nb][lk4 * 4 + 2][lr] = nav.z; As[nb][lk4 * 4 + 3][lr] = nav.w;
            Bs[nb][lk4 * 4 + 0][lr] = nbv.x; Bs[nb][lk4 * 4 + 1][lr] = nbv.y;
            Bs[nb][lk4 * 4 + 2][lr] = nbv.z; Bs[nb][lk4 * 4 + 3][lr] = nbv.w;
        }
        __syncthreads();
    }

    int c0 = bn + tc * 4;
    #pragma unroll
    for (int i = 0; i < 4; i++) {
        int r = bm + tr * 4 + i;
        if (r >= M) continue;
        float4 o;
        unpack2(acc[i][0], o.x, o.y);
        unpack2(acc[i][1], o.z, o.w);
        if (bias) {
            o.x += bias[c0 + 0]; o.y += bias[c0 + 1];
            o.z += bias[c0 + 2]; o.w += bias[c0 + 3];
        }
        if (act == 1) {
            o.x = fmaxf(o.x, 0.f); o.y = fmaxf(o.y, 0.f);
            o.z = fmaxf(o.z, 0.f); o.w = fmaxf(o.w, 0.f);
        }
        *(float4*)&C[(size_t)r * N + c0] = o;
    }
}

__global__ __launch_bounds__(256) void k_gemm6(const float* __restrict__ A, const float* __restrict__ B,
                                               const float* __restrict__ bias, float* __restrict__ C,
                                               int M, int N, int K, int act) {
    gemm6_body(A, B, bias, C, M, N, K, act, blockIdx.y, blockIdx.x);
}

// fused QKV: grid.x = 12 (3 weights x 4 col tiles), grid.y = 25
__global__ __launch_bounds__(256) void k_qkv(const float* __restrict__ A,
                                             const float* __restrict__ Wq, const float* __restrict__ Wk,
                                             const float* __restrict__ Wv,
                                             float* __restrict__ q, float* __restrict__ k, float* __restrict__ v) {
    int sel = blockIdx.x >> 2;
    const float* B = (sel == 0) ? Wq : (sel == 1) ? Wk : Wv;
    float* C = (sel == 0) ? q : (sel == 1) ? k : v;
    gemm6_body(A, B, nullptr, C, BS * NTOK, DMODEL, DMODEL, 0, blockIdx.y, blockIdx.x & 3);
}

// ---------------- per-window means of q,k,v (+ zero topk counters) ----------------
__global__ void k_means(const float* __restrict__ q, const float* __restrict__ k,
                        const float* __restrict__ v,
                        float* __restrict__ qm, float* __restrict__ km, float* __restrict__ vm,
                        int* __restrict__ icnt) {
    int b = blockIdx.x / NW, w = blockIdx.x % NW;
    int c = threadIdx.x;
    if (w == 0 && c < NW) icnt[b * NW + c] = 0;
    int wr = w / MW, wc = w % MW;
    float sq = 0.f, sk = 0.f, sv = 0.f;
    for (int p = 0; p < WS; p++) {
        int pr = p / WWIN, pc = p % WWIN;
        int n  = (wr * WWIN + pr) * HH + wc * WWIN + pc;
        int o  = (b * NTOK + n) * DMODEL + c;
        sq += q[o]; sk += k[o]; sv += v[o];
    }
    int o = (b * NW + w) * DMODEL + c;
    qm[o] = sq * (1.f / 49.f);
    km[o] = sk * (1.f / 49.f);
    vm[o] = sv * (1.f / 49.f);
}

// ---------------- topk via rank counting (exact jax top_k tie semantics) ----------------
// grid (NW, BS), 256 threads. Window j selected by query i iff rank(sim[i][j]) < 8,
// rank = #{u : s_u > s_j or (s_u == s_j and u < j)}.
__global__ __launch_bounds__(256) void k_topk(const float* __restrict__ qm, const float* __restrict__ km,
                                              int* __restrict__ icnt) {
    int i = blockIdx.x, b = blockIdx.y;
    __shared__ __align__(16) float4 q4s[64];
    __shared__ float red[NW][17];
    __shared__ float simr[NW];
    int t = threadIdx.x;
    if (t < 64) q4s[t] = ((const float4*)qm)[(b * NW + i) * 64 + t];
    __syncthreads();
    int j = t >> 4, part = t & 15;
    const float4* krow = (const float4*)km + (b * NW + j) * 64;
    float s = 0.f;
    #pragma unroll
    for (int u = 0; u < 4; u++) {
        float4 kk = krow[part * 4 + u];
        float4 qq = q4s[part * 4 + u];
        s += qq.x * kk.x + qq.y * kk.y + qq.z * kk.z + qq.w * kk.w;
    }
    red[j][part] = s;
    __syncthreads();
    if (part == 0) {
        float tot = 0.f;
        #pragma unroll
        for (int u = 0; u < 16; u++) tot += red[j][u];
        simr[j] = tot;
    }
    __syncthreads();
    if (t < NW) {
        float mine = simr[t];
        int rank = 0;
        #pragma unroll
        for (int u = 0; u < NW; u++) {
            float o = simr[u];
            rank += (o > mine) || (o == mine && u < t);
        }
        if (rank < KTOP) atomicAdd(&icnt[b * NW + t], 1);
    }
}

// ---------------- dedup attention over 800 unique keys (padded to 832) ----------------
// key row r: r<784 -> token r (weight = multiplicity of its window)
//            784<=r<800 -> mean r-784 (weight 16); r>=800 -> pad (weight 0)
// grid (7, NHEAD, BS*NCH2), block 128. Scores tiny -> softmax without max pass.
__global__ __launch_bounds__(128) void k_attn(const float* __restrict__ qb,
                                              const float* __restrict__ kb,
                                              const float* __restrict__ vb,
                                              const float* __restrict__ km,
                                              const float* __restrict__ vm,
                                              const int* __restrict__ icnt,
                                              float* __restrict__ pl,
                                              float* __restrict__ pacc) {
    int qt0   = blockIdx.x * 128;
    int h     = blockIdx.y;
    int b     = blockIdx.z / NCH2;
    int chunk = blockIdx.z % NCH2;
    int t = threadIdx.x;
    int l = qt0 + t;
    int lq = (l < NTOK) ? l : 0;
    int w = lq / WS, p = lq % WS;
    int n = ((w / MW) * WWIN + p / WWIN) * HH + (w % MW) * WWIN + (p % WWIN);

    const ulonglong2* qrow = (const ulonglong2*)(qb + ((size_t)(b * NTOK + n) * DMODEL + h * DH));
    ull qp[16];
    #pragma unroll
    for (int i = 0; i < 8; i++) {
        ulonglong2 qq = qrow[i];
        qp[2 * i + 0] = qq.x;
        qp[2 * i + 1] = qq.y;
    }

    __shared__ __align__(16) float4 Ks[KT][DH / 4];
    __shared__ __align__(16) float4 Vs[KT][DH / 4];
    __shared__ float  wgt[KT];
    __shared__ float  scnt[NW];
    if (t < NW) scnt[t] = (float)icnt[b * NW + t];

    float lsum = 0.f;
    ull acc[16];
    #pragma unroll
    for (int d = 0; d < 16; d++) acc[d] = 0ull;
    const float scale = 0.17677669529663687f;   // 32^-0.5

    int s0 = chunk * CH2;
    for (int tile = 0; tile < CH2 / KT; tile++) {
        int sbase = s0 + tile * KT;
        __syncthreads();
        // load 2*KT rows x 8 float4 = 256 float4, 128 threads -> 2 each
        #pragma unroll
        for (int i = 0; i < 2; i++) {
            int f = i * 128 + t;
            int r = f >> 3, c4 = f & 7;
            int rr = (r < KT) ? r : r - KT;
            int gr = sbase + rr;
            const float4* src;
            int rowbase;
            if (gr < NTOK) {
                src = (r < KT) ? (const float4*)kb : (const float4*)vb;
                rowbase = b * NTOK + gr;
            } else {
                int mi = gr - NTOK;
                if (mi >= NW) mi = 0;            // pad rows: weight 0, data harmless
                src = (r < KT) ? (const float4*)km : (const float4*)vm;
                rowbase = b * NW + mi;
            }
            float4 val = src[rowbase * (DMODEL / 4) + h * (DH / 4) + c4];
            if (r < KT) Ks[r][c4] = val; else Vs[r - KT][c4] = val;
        }
        if (t < KT) {
            int gr = sbase + t;
            float wv;
            if (gr < NTOK) {
                int win = (gr / (WWIN * HH)) * MW + (gr % HH) / WWIN;
                wv = scnt[win];
            } else wv = (gr < NTOK + NW) ? 16.f : 0.f;
            wgt[t] = wv;
        }
        __syncthreads();
        #pragma unroll 8
        for (int kk = 0; kk < KT; kk++) {
            const ulonglong2* krow = (const ulonglong2*)&Ks[kk][0];
            // 4 independent packed score chains (depth 4 instead of 16)
            ull sa = 0ull, sb = 0ull, sc = 0ull, sd = 0ull;
            #pragma unroll
            for (int c = 0; c < 2; c++) {
                ulonglong2 kv0 = krow[4 * c + 0];
                ulonglong2 kv1 = krow[4 * c + 1];
                ulonglong2 kv2 = krow[4 * c + 2];
                ulonglong2 kv3 = krow[4 * c + 3];
                ffma2(sa, qp[8 * c + 0], kv0.x); ffma2(sb, qp[8 * c + 1], kv0.y);
                ffma2(sc, qp[8 * c + 2], kv1.x); ffma2(sd, qp[8 * c + 3], kv1.y);
                ffma2(sa, qp[8 * c + 4], kv2.x); ffma2(sb, qp[8 * c + 5], kv2.y);
                ffma2(sc, qp[8 * c + 6], kv3.x); ffma2(sd, qp[8 * c + 7], kv3.y);
            }
            add2(sa, sb); add2(sc, sd); add2(sa, sc);
            float slo, shi;
            unpack2(sa, slo, shi);
            float pe = wgt[kk] * __expf((slo + shi) * scale);
            lsum += pe;
            ull pp = pack2(pe, pe);
            const ulonglong2* vrow = (const ulonglong2*)&Vs[kk][0];
            #pragma unroll
            for (int c = 0; c < 8; c++) {
                ulonglong2 vv = vrow[c];
                ffma2(acc[2 * c + 0], pp, vv.x);
                ffma2(acc[2 * c + 1], pp, vv.y);
            }
        }
    }
    if (l < NTOK) {
        int pbase = ((b * NHEAD + h) * NCH2 + chunk) * NTOK + l;
        pl[pbase] = lsum;
        #pragma unroll
        for (int d = 0; d < 16; d++) {
            float f0, f1;
            unpack2(acc[d], f0, f1);
            pacc[(size_t)pbase * DH + 2 * d + 0] = f0;
            pacc[(size_t)pbase * DH + 2 * d + 1] = f1;
        }
    }
}

// ---------------- combine split-K partials -> msg ----------------
__global__ void k_combine(const float* __restrict__ pl, const float* __restrict__ pacc,
                          float* __restrict__ msg) {
    int gq   = blockIdx.x * 8 + (threadIdx.x >> 5);   // BS*NHEAD*NTOK units
    int lane = threadIdx.x & 31;
    int b = gq / (NHEAD * NTOK);
    int rem = gq % (NHEAD * NTOK);
    int h = rem / NTOK, l = rem % NTOK;
    float Ls = 0.f, o = 0.f;
    #pragma unroll
    for (int c = 0; c < NCH2; c++) {
        int pbase = ((b * NHEAD + h) * NCH2 + c) * NTOK + l;
        Ls += pl[pbase];
        o  += pacc[(size_t)pbase * DH + lane];
    }
    msg[(b * NTOK + l) * DMODEL + h * DH + lane] = o / Ls;
}

// ---------------- LN1 + concat: message = [xf | LN(msg2)], shfl reductions ----------------
__global__ void k_ln1(const float* __restrict__ msg2, const float* __restrict__ xf,
                      const float* __restrict__ g, const float* __restrict__ bta,
                      float* __restrict__ message) {
    int row = blockIdx.x;       // 0..BS*NTOK-1
    int c = threadIdx.x;        // 256
    int lane = c & 31, wid = c >> 5;
    __shared__ float red[16];
    float v = msg2[row * DMODEL + c];
    float s = v;
    #pragma unroll
    for (int o = 16; o > 0; o >>= 1) s += __shfl_xor_sync(0xffffffff, s, o);
    if (lane == 0) red[wid] = s;
    __syncthreads();
    float mu = 0.f;
    #pragma unroll
    for (int u = 0; u < 8; u++) mu += red[u];
    mu *= (1.f / DMODEL);
    float dv = v - mu;
    float sq = dv * dv;
    #pragma unroll
    for (int o = 16; o > 0; o >>= 1) sq += __shfl_xor_sync(0xffffffff, sq, o);
    if (lane == 0) red[8 + wid] = sq;
    __syncthreads();
    float var = 0.f;
    #pragma unroll
    for (int u = 0; u < 8; u++) var += red[8 + u];
    var *= (1.f / DMODEL);
    float outv = dv * rsqrtf(var + 1e-5f) * g[c] + bta[c];
    message[row * DFF + DMODEL + c] = outv;
    message[row * DFF + c] = xf[row * DMODEL + c];
}

// ---------------- depthwise 3x3 conv + bias + exact gelu ----------------
__global__ void k_dwconv(const float* __restrict__ y1, const float* __restrict__ dww,
                         const float* __restrict__ dwb, float* __restrict__ y2) {
    int b = blockIdx.y;
    int nn = blockIdx.x;        // 0..783
    int c = threadIdx.x;        // 512
    int r = nn / HH, col = nn % HH;
    float s = 0.f;
    #pragma unroll
    for (int dr = -1; dr <= 1; dr++)
        #pragma unroll
        for (int dc = -1; dc <= 1; dc++) {
            int rr = r + dr, cc = col + dc;
            if (rr >= 0 && rr < HH && cc >= 0 && cc < HH)
                s += y1[(b * NTOK + rr * HH + cc) * DFF + c] * dww[c * 9 + (dr + 1) * 3 + (dc + 1)];
        }
    s += dwb[c];
    float gl = 0.5f * s * (1.f + erff(s * 0.70710678118654752f));
    y2[(b * NTOK + nn) * DFF + c] = gl;
}

// ---------------- LN2 + residual + coalesced transposed store ----------------
// grid (25, 2), block 256 (8 warps x 4 rows = 32 tokens per block)
__global__ __launch_bounds__(256) void k_ln2(const float* __restrict__ z, const float* __restrict__ xf,
                                             const float* __restrict__ g, const float* __restrict__ bta,
                                             float* __restrict__ out) {
    __shared__ float tile[DMODEL][33];
    int b = blockIdx.y, n0 = blockIdx.x * 32;
    int rows = NTOK - n0; if (rows > 32) rows = 32;
    int wid = threadIdx.x >> 5, lane = threadIdx.x & 31;

    #pragma unroll
    for (int i = 0; i < 4; i++) {
        int rl = wid * 4 + i;
        if (rl >= rows) break;
        int row = b * NTOK + n0 + rl;
        float vals[8];
        float s = 0.f;
        #pragma unroll
        for (int j = 0; j < 8; j++) {
            vals[j] = z[(size_t)row * DMODEL + lane + j * 32];
            s += vals[j];
        }
        #pragma unroll
        for (int o = 16; o > 0; o >>= 1) s += __shfl_xor_sync(0xffffffff, s, o);
        float mu = s * (1.f / DMODEL);
        float sq = 0.f;
        #pragma unroll
        for (int j = 0; j < 8; j++) { float d = vals[j] - mu; sq += d * d; }
        #pragma unroll
        for (int o = 16; o > 0; o >>= 1) sq += __shfl_xor_sync(0xffffffff, sq, o);
        float rs = rsqrtf(sq * (1.f / DMODEL) + 1e-5f);
        #pragma unroll
        for (int j = 0; j < 8; j++) {
            int c = lane + j * 32;
            float o2 = (vals[j] - mu) * rs * g[c] + bta[c] + xf[(size_t)row * DMODEL + c];
            tile[c][rl] = o2;
        }
    }
    __syncthreads();
    if (lane < rows) {
        #pragma unroll
        for (int i = 0; i < 32; i++) {
            int c = wid * 32 + i;
            out[((size_t)b * DMODEL + c) * NTOK + n0 + lane] = tile[c][lane];
        }
    }
}

// ---------------- host launcher ----------------
static float* symf(const void* s) { void* p = nullptr; cudaGetSymbolAddress(&p, s); return (float*)p; }

extern "C" void kernel_launch(void* const* d_in, const int* in_sizes, int n_in,
                              void* d_out, int out_size) {
    const float* x    = (const float*)d_in[0];
    const float* Wq   = (const float*)d_in[1];
    const float* Wk   = (const float*)d_in[2];
    const float* Wv   = (const float*)d_in[3];
    const float* Wm   = (const float*)d_in[4];
    const float* ln1g = (const float*)d_in[5];
    const float* ln1b = (const float*)d_in[6];
    const float* fc1w = (const float*)d_in[7];
    const float* fc1b = (const float*)d_in[8];
    const float* dww  = (const float*)d_in[9];
    const float* dwb  = (const float*)d_in[10];
    const float* fc2w = (const float*)d_in[11];
    const float* fc2b = (const float*)d_in[12];
    const float* ln2g = (const float*)d_in[13];
    const float* ln2b = (const float*)d_in[14];
    float* out = (float*)d_out;

    float* xf   = symf(g_xf);
    float* q    = symf(g_q);
    float* k    = symf(g_k);
    float* v    = symf(g_v);
    float* qm   = symf(g_qm);
    float* km   = symf(g_km);
    float* vm   = symf(g_vm);
    int*   icnt = (int*)symf(g_icnt);
    float* pl   = symf(g_pl);
    float* pacc = symf(g_pacc);
    float* msg  = symf(g_msg);
    float* msg2 = symf(g_msg2);
    float* mesg = symf(g_mesg);
    float* y1   = symf(g_y1);
    float* y2   = symf(g_y2);
    float* z    = symf(g_z);

    const int M = BS * NTOK;   // 1568

    k_transpose<<<dim3(25, 8, BS), dim3(32, 8)>>>(x, xf);

    k_qkv<<<dim3(12, 25), 256>>>(xf, Wq, Wk, Wv, q, k, v);

    k_means<<<BS * NW, DMODEL>>>(q, k, v, qm, km, vm, icnt);
    k_topk<<<dim3(NW, BS), 256>>>(qm, km, icnt);

    k_attn<<<dim3(7, NHEAD, BS * NCH2), 128>>>(q, k, v, km, vm, icnt, pl, pacc);
    k_combine<<<(BS * NHEAD * NTOK) / 8, 256>>>(pl, pacc, msg);

    k_gemm6<<<dim3(4, 25), 256>>>(msg, Wm, nullptr, msg2, M, DMODEL, DMODEL, 0);
    k_ln1<<<M, DMODEL>>>(msg2, xf, ln1g, ln1b, mesg);

    k_gemm6<<<dim3(8, 25), 256>>>(mesg, fc1w, fc1b, y1, M, DFF, DFF, 1);
    k_dwconv<<<dim3(NTOK, BS), DFF>>>(y1, dww, dwb, y2);
    k_gemm6<<<dim3(4, 25), 256>>>(y2, fc2w, fc2b, z, M, DMODEL, DFF, 0);

    k_ln2<<<dim3(25, BS), 256>>>(z, xf, ln2g, ln2b, out);
}